// round 11
// baseline (speedup 1.0000x reference)
#include <cuda_runtime.h>

// Scalar damped-Newton minimization of a degree-6 polynomial (serial, 1 thread).
// Exact reference semantics:
//   g2 = inf; while (g2 > 1e-12 && it < 100):
//     g=d1(x); h=d2(x); step = h>0 ? g/h : 0.1*g; x -= step; g2 = d1(x)^2
// (body always executes at least once; g at the top of body k equals g_new
//  from body k-1, so we carry it instead of recomputing).
//
// FINAL — overhead-bound, confirmed over 10 rounds:
//   ncu dur 4.0-4.6us = launch front-end + one dependent L2-latency load
//   chain + ~10-15 serial Newton iterations (~40 cyc each) + STG/EXIT tail,
//   all at un-ramped DVFS clocks. Bench dur_us adds ~2.3us graph-replay.
//   Identical source measured {6.40, 6.62, 6.62, 6.88} dur_us and
//   {4.06, 4.22, 4.61, 4.61} ncu across rounds -> remaining variation is
//   measurement noise, not code. All pipes <0.3% utilized; the serial
//   recurrence admits no parallel decomposition, and every residual
//   micro-lever (<0.1us) is 3-5x below the noise floor.
// Configuration:
//  - poly loaded as float4 + float2 + scalar (one cache line, 3 LDGs)
//  - Estrin evaluation (12-cyc dependent chains) for d1/d2
//  - rcp.approx.f32 + pred-as-data select for the damped-Newton step
//    (fixed point and exit test use exact FFMA math; rel_err measured 0.0)
//  - per-iter exact exit check overlapping the x-update chain

#define MAX_ITER 100
#define GRAD_SQ_TOL 1e-12f

__device__ __forceinline__ float fast_rcp(float v) {
    float r;
    asm("rcp.approx.f32 %0, %1;" : "=f"(r) : "f"(v));
    return r;
}

__global__ void polymin_kernel(const float4* __restrict__ poly4,
                               const float*  __restrict__ x_init,
                               float* __restrict__ out) {
    // poly: 7 fp32 lowest-degree-first. Load as 4+2+1.
    const float4 p0 = poly4[0];                                     // c0..c3
    const float2 p1 = ((const float2*)poly4)[2];                    // c4,c5
    const float  c6 = ((const float*)poly4)[6];
    const float  x0 = x_init[0];

    // d1 = p' (a0..a5), d2 = p'' (b0..b4)
    const float a0 = p0.y,        a1 = p0.z * 2.0f, a2 = p0.w * 3.0f,
                a3 = p1.x * 4.0f, a4 = p1.y * 5.0f, a5 = c6  * 6.0f;
    const float b0 = a1,          b1 = a2 * 2.0f,   b2 = a3 * 3.0f,
                b3 = a4 * 4.0f,   b4 = a5 * 5.0f;

    float x  = x0;
    float x2 = x * x;
    // g = d1(x) for the first body execution (reference always enters: g2=inf)
    float g  = fmaf(fmaf(fmaf(a5, x, a4), x2, fmaf(a3, x, a2)), x2,
                    fmaf(a1, x, a0));

    #pragma unroll 1
    for (int it = 0; it < MAX_ITER; ++it) {
        // h = d2(x), Estrin off (x, x2)
        const float h = fmaf(fmaf(b4, x2, fmaf(b3, x, b2)), x2,
                             fmaf(b1, x, b0));
        const float r   = fast_rcp(h);
        const float mul = (h > 0.0f) ? r : 0.1f;   // pred-as-data FSEL
        x  = fmaf(-g, mul, x);
        x2 = x * x;
        // g_new = d1(x_new); exit check overlaps next chain
        g  = fmaf(fmaf(fmaf(a5, x, a4), x2, fmaf(a3, x, a2)), x2,
                  fmaf(a1, x, a0));
        if (!(g * g > GRAD_SQ_TOL)) break;
    }

    out[0] = x;
}

extern "C" void kernel_launch(void* const* d_in, const int* in_sizes, int n_in,
                              void* d_out, int out_size) {
    const float4* poly   = (const float4*)d_in[0];  // 7 fp32
    const float*  x_init = (const float*)d_in[1];   // 1 fp32
    polymin_kernel<<<1, 1>>>(poly, x_init, (float*)d_out);
}

// round 12
// speedup vs baseline: 1.0539x; 1.0539x over previous
#include <cuda_runtime.h>

// Scalar damped-Newton minimization of a degree-6 polynomial (serial, 1 thread).
// Exact reference semantics:
//   g2 = inf; while (g2 > 1e-12 && it < 100):
//     g=d1(x); h=d2(x); step = h>0 ? g/h : 0.1*g; x -= step; g2 = d1(x)^2
// (body always executes at least once; g at the top of body k equals g_new
//  from body k-1, so we carry it instead of recomputing).
//
// FINAL — overhead-bound, confirmed over 11 rounds:
//   Identical source measured dur_us {6.40, 6.62, 6.62, 6.88, 6.88} and ncu
//   {4.06, 4.22, 4.26, 4.61, 4.61}: variation is measurement noise
//   (dur_us quantized to ~0.24us steps), not code. The ~4.2us ncu time is
//   launch front-end + one dependent L2-latency load chain + ~10-15 serial
//   Newton iterations (~40 cyc critical path each) + STG/EXIT tail at
//   un-ramped DVFS clocks; dur_us adds ~2.3us graph-replay machinery.
//   All pipes <0.3%. The recurrence is strictly serial (no parallel
//   decomposition shortens the chain); all residual micro-levers are
//   <=0.1us, 3-5x below the noise floor.
// Configuration:
//  - poly loaded as float4 + float2 + scalar (one cache line, 3 LDGs)
//  - Estrin evaluation (12-cyc dependent chains) for d1/d2
//  - rcp.approx.f32 + pred-as-data select for the damped-Newton step
//    (fixed point and exit test use exact FFMA math; rel_err measured 0.0)
//  - per-iter exact exit check overlapping the x-update chain

#define MAX_ITER 100
#define GRAD_SQ_TOL 1e-12f

__device__ __forceinline__ float fast_rcp(float v) {
    float r;
    asm("rcp.approx.f32 %0, %1;" : "=f"(r) : "f"(v));
    return r;
}

__global__ void polymin_kernel(const float4* __restrict__ poly4,
                               const float*  __restrict__ x_init,
                               float* __restrict__ out) {
    // poly: 7 fp32 lowest-degree-first. Load as 4+2+1.
    const float4 p0 = poly4[0];                                     // c0..c3
    const float2 p1 = ((const float2*)poly4)[2];                    // c4,c5
    const float  c6 = ((const float*)poly4)[6];
    const float  x0 = x_init[0];

    // d1 = p' (a0..a5), d2 = p'' (b0..b4)
    const float a0 = p0.y,        a1 = p0.z * 2.0f, a2 = p0.w * 3.0f,
                a3 = p1.x * 4.0f, a4 = p1.y * 5.0f, a5 = c6  * 6.0f;
    const float b0 = a1,          b1 = a2 * 2.0f,   b2 = a3 * 3.0f,
                b3 = a4 * 4.0f,   b4 = a5 * 5.0f;

    float x  = x0;
    float x2 = x * x;
    // g = d1(x) for the first body execution (reference always enters: g2=inf)
    float g  = fmaf(fmaf(fmaf(a5, x, a4), x2, fmaf(a3, x, a2)), x2,
                    fmaf(a1, x, a0));

    #pragma unroll 1
    for (int it = 0; it < MAX_ITER; ++it) {
        // h = d2(x), Estrin off (x, x2)
        const float h = fmaf(fmaf(b4, x2, fmaf(b3, x, b2)), x2,
                             fmaf(b1, x, b0));
        const float r   = fast_rcp(h);
        const float mul = (h > 0.0f) ? r : 0.1f;   // pred-as-data FSEL
        x  = fmaf(-g, mul, x);
        x2 = x * x;
        // g_new = d1(x_new); exit check overlaps next chain
        g  = fmaf(fmaf(fmaf(a5, x, a4), x2, fmaf(a3, x, a2)), x2,
                  fmaf(a1, x, a0));
        if (!(g * g > GRAD_SQ_TOL)) break;
    }

    out[0] = x;
}

extern "C" void kernel_launch(void* const* d_in, const int* in_sizes, int n_in,
                              void* d_out, int out_size) {
    const float4* poly   = (const float4*)d_in[0];  // 7 fp32
    const float*  x_init = (const float*)d_in[1];   // 1 fp32
    polymin_kernel<<<1, 1>>>(poly, x_init, (float*)d_out);
}